// round 13
// baseline (speedup 1.0000x reference)
#include <cuda_runtime.h>
#include <cuda_bf16.h>
#include <math.h>
#include <stdint.h>

// ---------------------------------------------------------------------------
// Problem constants
// ---------------------------------------------------------------------------
#define Bm 256
#define Lm 200
#define Hm 768
#define Dm 64
#define NS 6
#define Mseq (Bm * Lm)          // 51200
#define NC 8                    // scan chunks
#define CL 25                   // Lm / NC
#define NEVB (Mseq / 128)       // 400 blocks for the sequence rows

typedef unsigned long long ull;

// ---------------------------------------------------------------------------
// Device scratch (static globals — no allocation allowed)
// ---------------------------------------------------------------------------
__device__ float g_E[(size_t)Mseq * Dm];            // E = ev@We+be
__device__ float g_G[(size_t)6 * Mseq * Dm];        // activated gates (gate, row, d)
__device__ float g_Hs[(size_t)Mseq * Dm];           // hidden states
__device__ float g_Ec[Bm * Dm];
__device__ float g_Gc[6 * Bm * Dm];
__device__ float g_Clast[Bm * Dm];
__device__ float g_Hcur[Bm * Dm];
__device__ float g_wt[384];                          // Wtime @ Wg_bot
__device__ float g_bias[384];                        // btime @ Wg_bot + bg
__device__ float g_scanP[Bm * Dm * NC];              // chunk prod(f)
__device__ float g_scanA[Bm * Dm * NC];              // chunk affine term
__device__ float g_scanCin[Bm * Dm * NC];            // chunk entry carry
__device__ unsigned g_WeHi[384 * 64];                // We split: packed bf16x2 (k pairs)
__device__ unsigned g_WeLo[384 * 64];
__device__ unsigned g_WgHi[32 * 384];                // Wg_top split: [kpair][n]
__device__ unsigned g_WgLo[32 * 384];

// ---------------------------------------------------------------------------
// Math helpers
// ---------------------------------------------------------------------------
__device__ __forceinline__ float fast_tanh(float x) {
    float y;
    asm("tanh.approx.f32 %0, %1;" : "=f"(y) : "f"(x));
    return y;
}
__device__ __forceinline__ float fsigmoid(float x) {
    return __fdividef(1.0f, 1.0f + __expf(-x));
}
__device__ __forceinline__ float fsoftplus(float x) {
    return fmaxf(x, 0.0f) + log1pf(__expf(-fabsf(x)));
}
__device__ __forceinline__ float fgelu(float x) {
    return 0.5f * x * (1.0f + erff(x * 0.70710678118654752f));
}
// pack two f32 -> bf16x2 (lo = first element in lower 16 bits)
__device__ __forceinline__ unsigned bfpair(float lo, float hi) {
    unsigned r;
    asm("cvt.rn.bf16x2.f32 %0, %1, %2;" : "=r"(r) : "f"(hi), "f"(lo));
    return r;
}
// split a float2 (consecutive-k pair) into hi/lo bf16x2 regs
__device__ __forceinline__ void split2(float2 e, unsigned& h, unsigned& l) {
    unsigned hp = bfpair(e.x, e.y);
    float h0 = __uint_as_float(hp << 16);
    float h1 = __uint_as_float(hp & 0xFFFF0000u);
    h = hp;
    l = bfpair(e.x - h0, e.y - h1);
}
__device__ __forceinline__ void mma_bf16(float* c, const unsigned* a, unsigned b0, unsigned b1) {
    asm volatile(
        "mma.sync.aligned.m16n8k16.row.col.f32.bf16.bf16.f32 "
        "{%0,%1,%2,%3}, {%4,%5,%6,%7}, {%8,%9}, {%0,%1,%2,%3};"
        : "+f"(c[0]), "+f"(c[1]), "+f"(c[2]), "+f"(c[3])
        : "r"(a[0]), "r"(a[1]), "r"(a[2]), "r"(a[3]), "r"(b0), "r"(b1));
}
__device__ __forceinline__ void cp_async16(void* sdst, const void* gsrc) {
    unsigned sa = (unsigned)__cvta_generic_to_shared(sdst);
    asm volatile("cp.async.cg.shared.global [%0], [%1], 16;" :: "r"(sa), "l"(gsrc) : "memory");
}

// ---------------------------------------------------------------------------
// Merged prologue kernel: one launch does setup + We split + Wg split.
//   items [0,384)            : wt/bias columns
//   items [384, 384+24576)   : We split (t = j*64+n)
//   items [24960, 24960+12288): Wg split (t = j*384+n)
// ---------------------------------------------------------------------------
__global__ __launch_bounds__(256) void prologue_kernel(const float* __restrict__ Wtime,
                                                       const float* __restrict__ btime,
                                                       const float* __restrict__ Wg,
                                                       const float* __restrict__ bg,
                                                       const float* __restrict__ We) {
    int t = blockIdx.x * 256 + threadIdx.x;
    if (t < 384) {
        int c = t;
        float s1 = 0.f, s2 = 0.f;
        #pragma unroll 8
        for (int d = 0; d < 64; d++) {
            float w = Wg[(size_t)(64 + d) * 384 + c];
            s1 += Wtime[d] * w;
            s2 += btime[d] * w;
        }
        g_wt[c] = s1;
        g_bias[c] = s2 + bg[c];
    } else if (t < 384 + 24576) {
        int u = t - 384;
        int j = u >> 6, n = u & 63;
        float2 e = make_float2(We[(size_t)(2 * j) * 64 + n], We[(size_t)(2 * j + 1) * 64 + n]);
        unsigned h, l;
        split2(e, h, l);
        g_WeHi[u] = h;
        g_WeLo[u] = l;
    } else if (t < 384 + 24576 + 12288) {
        int u = t - (384 + 24576);
        int j = u / 384, n = u - j * 384;
        float2 e = make_float2(Wg[(size_t)(2 * j) * 384 + n], Wg[(size_t)(2 * j + 1) * 384 + n]);
        unsigned h, l;
        split2(e, h, l);
        g_WgHi[u] = h;
        g_WgLo[u] = l;
    }
}

// ---------------------------------------------------------------------------
// GEMM1 via bf16-split tensor-core mma + 3-buffer cp.async pipeline
// (prefetch distance 2). Retiled: 8 warps = 8 m-tiles, each warp covers
// 16 rows x 64 cols — every A row split by exactly ONE warp (was 2).
// MERGED: blocks [0,NEVB) = event rows, [NEVB,NEVB+2) = cls rows.
// ---------------------------------------------------------------------------
#define G1_LOAD(s, t) do {                                                        \
    int k0_ = (t) * 16;                                                           \
    {   int m_ = tid >> 2, kv_ = (tid & 3) * 4;                                   \
        cp_async16(&As[s][m_][kv_], A + (r0 + m_) * 768 + k0_ + kv_); }           \
    {   int c_ = tid + 256;                                                       \
        int m_ = c_ >> 2, kv_ = (c_ & 3) * 4;                                     \
        cp_async16(&As[s][m_][kv_], A + (r0 + m_) * 768 + k0_ + kv_); }           \
    if (tid < 128) {                                                              \
        int j_ = tid >> 4, n_ = (tid & 15) * 4;                                   \
        cp_async16(&BsH[s][j_][n_], BHi + (size_t)(t) * 512 + j_ * 64 + n_);      \
    } else {                                                                      \
        int j_ = (tid - 128) >> 4, n_ = ((tid - 128) & 15) * 4;                   \
        cp_async16(&BsL[s][j_][n_], BLo + (size_t)(t) * 512 + j_ * 64 + n_);      \
    }                                                                             \
} while (0)

__global__ __launch_bounds__(256, 3) void gemm1_mma(const float* __restrict__ Aev,
                                                    const float* __restrict__ Acls,
                                                    const unsigned* __restrict__ BHi,
                                                    const unsigned* __restrict__ BLo,
                                                    const float* __restrict__ be,
                                                    float* __restrict__ Cev,
                                                    float* __restrict__ Ccls) {
    __shared__ __align__(16) float As[3][128][20];        // 30.0 KB
    __shared__ __align__(16) unsigned BsH[3][8][64];      // 6.0 KB
    __shared__ __align__(16) unsigned BsL[3][8][64];      // 6.0 KB
    const int tid = threadIdx.x;
    const int wid = tid >> 5, lane = tid & 31;
    const int q = lane & 3, rr = lane >> 2;
    const int rowb = wid * 16 + rr;      // warp = m-tile wid: rows wid*16 .. +15

    const float* A;
    float* C;
    size_t r0;
    if (blockIdx.x < NEVB) {
        A = Aev;  C = Cev;  r0 = (size_t)blockIdx.x * 128;
    } else {
        A = Acls; C = Ccls; r0 = (size_t)(blockIdx.x - NEVB) * 128;
    }

    float acc[8][4];
    #pragma unroll
    for (int nt = 0; nt < 8; nt++)
        #pragma unroll
        for (int i = 0; i < 4; i++) acc[nt][i] = 0.f;

    // prologue: stages 0 and 1 in flight
    G1_LOAD(0, 0);
    asm volatile("cp.async.commit_group;" ::: "memory");
    G1_LOAD(1, 1);
    asm volatile("cp.async.commit_group;" ::: "memory");

    #pragma unroll 3
    for (int t = 0; t < 48; t++) {
        const int cur = t % 3;
        asm volatile("cp.async.wait_group 1;" ::: "memory");   // stage t resident
        __syncthreads();                                        // all warps past stage t-1 reads

        // issue stage t+2 into buffer (t+2)%3 (read finished at iter t-1)
        if (t + 2 < 48) {
            const int nxt = (t + 2) % 3;
            G1_LOAD(nxt, t + 2);
        }
        asm volatile("cp.async.commit_group;" ::: "memory");    // (possibly empty) group

        // A fragments: 4 splits per thread (unique rows per warp)
        unsigned aH[4], aL[4];
        {
            float2 e0 = *reinterpret_cast<const float2*>(&As[cur][rowb][2 * q]);
            float2 e1 = *reinterpret_cast<const float2*>(&As[cur][rowb + 8][2 * q]);
            float2 e2 = *reinterpret_cast<const float2*>(&As[cur][rowb][2 * q + 8]);
            float2 e3 = *reinterpret_cast<const float2*>(&As[cur][rowb + 8][2 * q + 8]);
            split2(e0, aH[0], aL[0]);
            split2(e1, aH[1], aL[1]);
            split2(e2, aH[2], aL[2]);
            split2(e3, aH[3], aL[3]);
        }
        #pragma unroll
        for (int nt = 0; nt < 8; nt++) {
            int c = nt * 8 + rr;
            unsigned bH0 = BsH[cur][q][c], bH1 = BsH[cur][q + 4][c];
            unsigned bL0 = BsL[cur][q][c], bL1 = BsL[cur][q + 4][c];
            mma_bf16(acc[nt], aH, bH0, bH1);
            mma_bf16(acc[nt], aH, bL0, bL1);
            mma_bf16(acc[nt], aL, bH0, bH1);
        }
    }

    // epilogue: + be, direct float2 stores
    #pragma unroll
    for (int nt = 0; nt < 8; nt++) {
        int col = nt * 8 + 2 * q;
        float b0 = be[col], b1 = be[col + 1];
        size_t row = r0 + rowb;
        *reinterpret_cast<float2*>(C + row * 64 + col) =
            make_float2(acc[nt][0] + b0, acc[nt][1] + b1);
        *reinterpret_cast<float2*>(C + (row + 8) * 64 + col) =
            make_float2(acc[nt][2] + b0, acc[nt][3] + b1);
    }
}

// ---------------------------------------------------------------------------
// GEMM2 via bf16-split tensor-core mma (unchanged from R11)
// ---------------------------------------------------------------------------
__global__ __launch_bounds__(256, 2) void gemm2_mma(const float* __restrict__ Eev,
                                                    const float* __restrict__ Ecls,
                                                    const unsigned* __restrict__ WgHi,
                                                    const unsigned* __restrict__ WgLo,
                                                    const float* __restrict__ days_in,
                                                    float* __restrict__ Gev,
                                                    float* __restrict__ Gcls) {
    __shared__ unsigned AsH[128][33], AsL[128][33];
    __shared__ __align__(16) unsigned BsH[8][132], BsL[8][132];
    const int tid = threadIdx.x;
    const int wid = tid >> 5, lane = tid & 31;
    const int warpR = wid >> 1;
    const int warpC = wid & 1;
    const int q = lane & 3, rr = lane >> 2;
    const int n0 = blockIdx.y * 128;

    const float* E;
    const float* days;
    float* gates;
    int M;
    size_t r0;
    if (blockIdx.x < NEVB) {
        E = Eev;  days = days_in; gates = Gev;  M = Mseq;
        r0 = (size_t)blockIdx.x * 128;
    } else {
        E = Ecls; days = nullptr; gates = Gcls; M = Bm;
        r0 = (size_t)(blockIdx.x - NEVB) * 128;
    }

    #pragma unroll
    for (int p = 0; p < 16; p++) {
        int idx = tid + p * 256;
        int m = idx >> 5, j = idx & 31;
        float2 e = *reinterpret_cast<const float2*>(E + (r0 + m) * 64 + 2 * j);
        unsigned h, l;
        split2(e, h, l);
        AsH[m][j] = h;
        AsL[m][j] = l;
    }

    float acc[2][8][4];
    #pragma unroll
    for (int mt = 0; mt < 2; mt++)
        #pragma unroll
        for (int nt = 0; nt < 8; nt++)
            #pragma unroll
            for (int i = 0; i < 4; i++) acc[mt][nt][i] = 0.f;

    #pragma unroll
    for (int c = 0; c < 4; c++) {
        __syncthreads();
        {
            int t4 = tid * 4;
            int jj = t4 >> 7, nn = t4 & 127;
            size_t src = (size_t)(c * 8 + jj) * 384 + n0 + nn;
            *reinterpret_cast<uint4*>(&BsH[jj][nn]) = *reinterpret_cast<const uint4*>(WgHi + src);
            *reinterpret_cast<uint4*>(&BsL[jj][nn]) = *reinterpret_cast<const uint4*>(WgLo + src);
        }
        __syncthreads();

        unsigned aH[2][4], aL[2][4];
        const int jb = c * 8;
        #pragma unroll
        for (int mt = 0; mt < 2; mt++) {
            int row = warpR * 32 + mt * 16 + rr;
            aH[mt][0] = AsH[row][jb + q];         aL[mt][0] = AsL[row][jb + q];
            aH[mt][1] = AsH[row + 8][jb + q];     aL[mt][1] = AsL[row + 8][jb + q];
            aH[mt][2] = AsH[row][jb + q + 4];     aL[mt][2] = AsL[row][jb + q + 4];
            aH[mt][3] = AsH[row + 8][jb + q + 4]; aL[mt][3] = AsL[row + 8][jb + q + 4];
        }
        #pragma unroll
        for (int nt = 0; nt < 8; nt++) {
            int cc = warpC * 64 + nt * 8 + rr;
            unsigned bH0 = BsH[q][cc], bH1 = BsH[q + 4][cc];
            unsigned bL0 = BsL[q][cc], bL1 = BsL[q + 4][cc];
            #pragma unroll
            for (int mt = 0; mt < 2; mt++) {
                mma_bf16(acc[mt][nt], aH[mt], bH0, bH1);
                mma_bf16(acc[mt][nt], aH[mt], bL0, bL1);
                mma_bf16(acc[mt][nt], aL[mt], bH0, bH1);
            }
        }
    }

    const int gate = (n0 + warpC * 64) >> 6;
    float wt16[8][2], bi16[8][2];
    #pragma unroll
    for (int nt = 0; nt < 8; nt++) {
        int col = n0 + warpC * 64 + nt * 8 + 2 * q;
        wt16[nt][0] = g_wt[col];   wt16[nt][1] = g_wt[col + 1];
        bi16[nt][0] = g_bias[col]; bi16[nt][1] = g_bias[col + 1];
    }
    const int d0 = 2 * q;
    #pragma unroll
    for (int mt = 0; mt < 2; mt++) {
        size_t rowb = r0 + warpR * 32 + mt * 16 + rr;
        #pragma unroll
        for (int h = 0; h < 2; h++) {
            size_t rg = rowb + h * 8;
            float dy = days ? days[rg] : 0.f;
            float v[16];
            #pragma unroll
            for (int nt = 0; nt < 8; nt++) {
                v[2 * nt + 0] = acc[mt][nt][2 * h + 0] + bi16[nt][0] + dy * wt16[nt][0];
                v[2 * nt + 1] = acc[mt][nt][2 * h + 1] + bi16[nt][1] + dy * wt16[nt][1];
            }
            if (gate == 2) {
                #pragma unroll
                for (int i = 0; i < 16; i++) v[i] = fast_tanh(v[i]);
            } else if (gate == 4) {
                #pragma unroll
                for (int i = 0; i < 16; i++) v[i] = fsoftplus(v[i]);
            } else if (gate != 5) {
                #pragma unroll
                for (int i = 0; i < 16; i++) v[i] = fsigmoid(v[i]);
            }
            float* dst = gates + ((size_t)gate * M + rg) * 64 + d0;
            #pragma unroll
            for (int nt = 0; nt < 8; nt++)
                *reinterpret_cast<float2*>(dst + nt * 8) = make_float2(v[2 * nt], v[2 * nt + 1]);
        }
    }
}

// ---------------------------------------------------------------------------
// Chunk-parallel CT-LSTM scan (unchanged)
// ---------------------------------------------------------------------------
__global__ __launch_bounds__(256) void scanA_kernel(const float* __restrict__ gates) {
    int t = blockIdx.x * 256 + threadIdx.x;
    int d = t & 63, rest = t >> 6;
    int b = rest & 255, ch = rest >> 8;
    const size_t S = (size_t)Mseq * 64;
    size_t base = ((size_t)(b * Lm + ch * CL)) * 64 + d;
    float c = 0.f, P = 1.f;
    #pragma unroll 5
    for (int l = 0; l < CL; l++) {
        size_t idx = base + (size_t)l * 64;
        float i_ = gates[idx];
        float f_ = gates[S + idx];
        float z_ = gates[2 * S + idx];
        c = f_ * c + i_ * z_;
        P *= f_;
    }
    g_scanA[t] = c;
    g_scanP[t] = P;
}

__global__ __launch_bounds__(256) void scanB_kernel() {
    int t = blockIdx.x * 256 + threadIdx.x;
    float c = 0.f;
    #pragma unroll
    for (int ch = 0; ch < NC; ch++) {
        int q = ch * 16384 + t;
        g_scanCin[q] = c;
        c = g_scanP[q] * c + g_scanA[q];
    }
    g_Clast[t] = c;
}

__global__ __launch_bounds__(256) void scanC_kernel(const float* __restrict__ gates,
                                                    const float* __restrict__ days) {
    int t = blockIdx.x * 256 + threadIdx.x;
    int d = t & 63, rest = t >> 6;
    int b = rest & 255, ch = rest >> 8;
    const size_t S = (size_t)Mseq * 64;
    size_t base = ((size_t)(b * Lm + ch * CL)) * 64 + d;
    const float* dptr = days + b * Lm + ch * CL;
    float c = g_scanCin[t];
    #pragma unroll 5
    for (int l = 0; l < CL; l++) {
        size_t idx = base + (size_t)l * 64;
        float i_ = gates[idx];
        float f_ = gates[S + idx];
        float z_ = gates[2 * S + idx];
        float o_ = gates[3 * S + idx];
        float dl = gates[4 * S + idx];
        float cb = gates[5 * S + idx];
        float dt = fmaxf(dptr[l], 0.f);
        c = f_ * c + i_ * z_;
        float e = __expf(-dl * dt);
        float cd = cb + (c - cb) * e;
        g_Hs[idx] = o_ * fast_tanh(cd);
    }
}

// ---------------------------------------------------------------------------
// Final CT-LSTM step at dt = 0
// ---------------------------------------------------------------------------
__global__ void final_ch_kernel() {
    int b = blockIdx.x, d = threadIdx.x;
    const int S = Bm * 64;
    int idx = b * 64 + d;
    float c = g_Gc[S + idx] * g_Clast[idx] + g_Gc[idx] * g_Gc[2 * S + idx];
    g_Hcur[idx] = g_Gc[3 * S + idx] * fast_tanh(c);
}

// ---------------------------------------------------------------------------
// Intensity MLP (unchanged; Ys aliased into rows buffer)
// ---------------------------------------------------------------------------
__global__ __launch_bounds__(256) void intensity_kernel(const float* __restrict__ src, int M,
                                                        const float* __restrict__ W1,
                                                        const float* __restrict__ b1,
                                                        const float* __restrict__ W2,
                                                        const float* __restrict__ b2,
                                                        float* __restrict__ out) {
    __shared__ __align__(16) float rows[128][68];
    __shared__ __align__(16) float W1s[2048];
    __shared__ float W2s[192], b1s[32], b2s[6];
    float* Ys = &rows[0][0];
    int tid = threadIdx.x;
    size_t r0 = (size_t)blockIdx.x * 128;

    for (int i4 = tid; i4 < 512; i4 += 256)
        *reinterpret_cast<float4*>(&W1s[i4 * 4]) = reinterpret_cast<const float4*>(W1)[i4];
    if (tid < 192) W2s[tid] = W2[tid];
    if (tid < 32) b1s[tid] = b1[tid];
    if (tid < 6) b2s[tid] = b2[tid];
    #pragma unroll
    for (int p = 0; p < 8; p++) {
        int idx = tid + p * 256;
        int m = idx >> 4, dv = (idx & 15) * 4;
        *reinterpret_cast<float4*>(&rows[m][dv]) =
            *reinterpret_cast<const float4*>(src + (r0 + m) * 64 + dv);
    }
    __syncthreads();

    int tr = tid >> 3, tc = tid & 7;
    float acc[4][4];
    #pragma unroll
    for (int i = 0; i < 4; i++)
        #pragma unroll
        for (int j = 0; j < 4; j++) acc[i][j] = b1s[tc * 4 + j];
    #pragma unroll 4
    for (int k = 0; k < 64; k++) {
        float4 w = *reinterpret_cast<const float4*>(&W1s[k * 32 + tc * 4]);
        float a0 = rows[tr * 4 + 0][k];
        float a1 = rows[tr * 4 + 1][k];
        float a2 = rows[tr * 4 + 2][k];
        float a3 = rows[tr * 4 + 3][k];
        acc[0][0] = fmaf(a0, w.x, acc[0][0]); acc[0][1] = fmaf(a0, w.y, acc[0][1]);
        acc[0][2] = fmaf(a0, w.z, acc[0][2]); acc[0][3] = fmaf(a0, w.w, acc[0][3]);
        acc[1][0] = fmaf(a1, w.x, acc[1][0]); acc[1][1] = fmaf(a1, w.y, acc[1][1]);
        acc[1][2] = fmaf(a1, w.z, acc[1][2]); acc[1][3] = fmaf(a1, w.w, acc[1][3]);
        acc[2][0] = fmaf(a2, w.x, acc[2][0]); acc[2][1] = fmaf(a2, w.y, acc[2][1]);
        acc[2][2] = fmaf(a2, w.z, acc[2][2]); acc[2][3] = fmaf(a2, w.w, acc[2][3]);
        acc[3][0] = fmaf(a3, w.x, acc[3][0]); acc[3][1] = fmaf(a3, w.y, acc[3][1]);
        acc[3][2] = fmaf(a3, w.z, acc[3][2]); acc[3][3] = fmaf(a3, w.w, acc[3][3]);
    }
    __syncthreads();
    #pragma unroll
    for (int i = 0; i < 4; i++)
        #pragma unroll
        for (int j = 0; j < 4; j++)
            Ys[(tr * 4 + i) * 33 + tc * 4 + j] = fgelu(acc[i][j]);
    __syncthreads();

    if (tid < 128) {
        int row = tid;
        float o6[6];
        #pragma unroll
        for (int c = 0; c < 6; c++) o6[c] = b2s[c];
        #pragma unroll 4
        for (int k = 0; k < 32; k++) {
            float a = Ys[row * 33 + k];
            #pragma unroll
            for (int c = 0; c < 6; c++) o6[c] = fmaf(a, W2s[k * 6 + c], o6[c]);
        }
        #pragma unroll
        for (int c = 0; c < 6; c++) out[(r0 + row) * 6 + c] = fsoftplus(o6[c]);
    }
}

// ---------------------------------------------------------------------------
// TTE head (unchanged)
// ---------------------------------------------------------------------------
__global__ __launch_bounds__(256) void tte_kernel(const float* __restrict__ W1,
                                                  const float* __restrict__ b1,
                                                  const float* __restrict__ W2,
                                                  const float* __restrict__ b2,
                                                  float* __restrict__ out) {
    __shared__ float W1s[64 * 32];
    __shared__ float W2s[32];
    __shared__ float b1s[32];
    __shared__ float b2s0;
    __shared__ float rows[8][64];
    int tid = threadIdx.x;
    for (int i = tid; i < 2048; i += 256) W1s[i] = W1[i];
    if (tid < 32) { W2s[tid] = W2[tid]; b1s[tid] = b1[tid]; }
    if (tid == 0) b2s0 = b2[0];
    __syncthreads();
    int warp = tid >> 5, lane = tid & 31;
    int b = blockIdx.x * 8 + warp;
    if (b >= Bm) return;
    rows[warp][lane] = g_Hcur[b * 64 + lane];
    rows[warp][lane + 32] = g_Hcur[b * 64 + lane + 32];
    __syncwarp();
    float acc = b1s[lane];
    #pragma unroll
    for (int k = 0; k < 64; k++) acc = fmaf(rows[warp][k], W1s[k * 32 + lane], acc);
    float y = fgelu(acc);
    float p = y * W2s[lane];
    #pragma unroll
    for (int off = 16; off; off >>= 1) p += __shfl_xor_sync(0xffffffffu, p, off);
    if (lane == 0) out[b] = fsoftplus(p + b2s0);
}

// ---------------------------------------------------------------------------
// Direct head + softmax (unchanged)
// ---------------------------------------------------------------------------
__global__ __launch_bounds__(384) void direct_kernel(const float* __restrict__ cls,
                                                     const float* __restrict__ Ws1,
                                                     const float* __restrict__ bs1,
                                                     const float* __restrict__ Ws2,
                                                     const float* __restrict__ bs2,
                                                     const float* __restrict__ ci,
                                                     float* __restrict__ probs) {
    __shared__ float cls_s[4 * 768];
    __shared__ float s1[4][384];
    __shared__ float logit_s[4][6];
    int tid = threadIdx.x;
    int b0 = blockIdx.x * 4;
    for (int idx = tid; idx < 4 * 768; idx += 384)
        cls_s[idx] = cls[(size_t)b0 * 768 + idx];
    __syncthreads();
    float a0 = bs1[tid], a1 = a0, a2 = a0, a3 = a0;
    #pragma unroll 4
    for (int k = 0; k < 768; k++) {
        float w = Ws1[(size_t)k * 384 + tid];
        a0 = fmaf(cls_s[k], w, a0);
        a1 = fmaf(cls_s[768 + k], w, a1);
        a2 = fmaf(cls_s[1536 + k], w, a2);
        a3 = fmaf(cls_s[2304 + k], w, a3);
    }
    s1[0][tid] = fgelu(a0);
    s1[1][tid] = fgelu(a1);
    s1[2][tid] = fgelu(a2);
    s1[3][tid] = fgelu(a3);
    __syncthreads();
    int w = tid >> 5, lane = tid & 31;
    if (w < 6) {
        for (int g = 0; g < 4; g++) {
            float p = 0.f;
            #pragma unroll
            for (int j = lane; j < 384; j += 32) p = fmaf(s1[g][j], Ws2[(size_t)j * 6 + w], p);
            #pragma unroll
            for (int off = 16; off; off >>= 1) p += __shfl_xor_sync(0xffffffffu, p, off);
            if (lane == 0) logit_s[g][w] = p + bs2[w];
        }
    }
    __syncthreads();
    if (tid < 4) {
        int g = tid;
        float x[6], m = -1e30f;
        #pragma unroll
        for (int c = 0; c < 6; c++) {
            x[c] = logit_s[g][c] + logf(ci[(size_t)(b0 + g) * 6 + c]);
            m = fmaxf(m, x[c]);
        }
        float s = 0.f;
        #pragma unroll
        for (int c = 0; c < 6; c++) { x[c] = __expf(x[c] - m); s += x[c]; }
        float inv = __fdividef(1.f, s);
        #pragma unroll
        for (int c = 0; c < 6; c++) probs[(size_t)(b0 + g) * 6 + c] = x[c] * inv;
    }
}

// ---------------------------------------------------------------------------
// Launch
// ---------------------------------------------------------------------------
extern "C" void kernel_launch(void* const* d_in, const int* in_sizes, int n_in,
                              void* d_out, int out_size) {
    const float* cls   = (const float*)d_in[0];
    const float* ev    = (const float*)d_in[1];
    const float* days  = (const float*)d_in[2];
    const float* We    = (const float*)d_in[3];
    const float* be    = (const float*)d_in[4];
    const float* Wtime = (const float*)d_in[5];
    const float* btime = (const float*)d_in[6];
    const float* Wg    = (const float*)d_in[7];
    const float* bg    = (const float*)d_in[8];
    const float* Wi1   = (const float*)d_in[9];
    const float* bi1   = (const float*)d_in[10];
    const float* Wi2   = (const float*)d_in[11];
    const float* bi2   = (const float*)d_in[12];
    const float* Ws1   = (const float*)d_in[13];
    const float* bs1   = (const float*)d_in[14];
    const float* Ws2   = (const float*)d_in[15];
    const float* bs2   = (const float*)d_in[16];
    const float* Wq1   = (const float*)d_in[17];
    const float* bq1   = (const float*)d_in[18];
    const float* Wq2   = (const float*)d_in[19];
    const float* bq2   = (const float*)d_in[20];

    float* out = (float*)d_out;
    float* out_probs = out;
    float* out_tte   = out + 1536;
    float* out_ci    = out + 1536 + 256;
    float* out_hist  = out + 1536 + 256 + 1536;

    float *pE, *pG, *pEc, *pGc, *pHs, *pHcur;
    unsigned *pWeHi, *pWeLo, *pWgHi, *pWgLo;
    cudaGetSymbolAddress((void**)&pE, g_E);
    cudaGetSymbolAddress((void**)&pG, g_G);
    cudaGetSymbolAddress((void**)&pEc, g_Ec);
    cudaGetSymbolAddress((void**)&pGc, g_Gc);
    cudaGetSymbolAddress((void**)&pHs, g_Hs);
    cudaGetSymbolAddress((void**)&pHcur, g_Hcur);
    cudaGetSymbolAddress((void**)&pWeHi, g_WeHi);
    cudaGetSymbolAddress((void**)&pWeLo, g_WeLo);
    cudaGetSymbolAddress((void**)&pWgHi, g_WgHi);
    cudaGetSymbolAddress((void**)&pWgLo, g_WgLo);

    prologue_kernel<<<146, 256>>>(Wtime, btime, Wg, bg, We);

    gemm1_mma<<<NEVB + 2, 256>>>(ev, cls, pWeHi, pWeLo, be, pE, pEc);
    gemm2_mma<<<dim3(NEVB + 2, 3), 256>>>(pE, pEc, pWgHi, pWgLo, days, pG, pGc);

    scanA_kernel<<<(Bm * Dm * NC) / 256, 256>>>(pG);
    scanB_kernel<<<(Bm * Dm) / 256, 256>>>();
    scanC_kernel<<<(Bm * Dm * NC) / 256, 256>>>(pG, days);
    final_ch_kernel<<<Bm, 64>>>();

    intensity_kernel<<<Mseq / 128, 256>>>(pHs, Mseq, Wi1, bi1, Wi2, bi2, out_hist);
    intensity_kernel<<<Bm / 128, 256>>>(pHcur, Bm, Wi1, bi1, Wi2, bi2, out_ci);
    tte_kernel<<<Bm / 8, 256>>>(Wq1, bq1, Wq2, bq2, out_tte);
    direct_kernel<<<Bm / 4, 384>>>(cls, Ws1, bs1, Ws2, bs2, out_ci, out_probs);
}

// round 14
// speedup vs baseline: 1.0170x; 1.0170x over previous
#include <cuda_runtime.h>
#include <cuda_bf16.h>
#include <math.h>
#include <stdint.h>

// ---------------------------------------------------------------------------
// Problem constants
// ---------------------------------------------------------------------------
#define Bm 256
#define Lm 200
#define Hm 768
#define Dm 64
#define NS 6
#define Mseq (Bm * Lm)          // 51200
#define NC 8                    // scan chunks
#define CL 25                   // Lm / NC
#define NEVB (Mseq / 128)       // 400 blocks for the sequence rows

typedef unsigned long long ull;

// ---------------------------------------------------------------------------
// Device scratch (static globals — no allocation allowed)
// ---------------------------------------------------------------------------
__device__ float g_E[(size_t)Mseq * Dm];            // E = ev@We+be
__device__ float g_G[(size_t)6 * Mseq * Dm];        // activated gates (gate, row, d)
__device__ float g_Hs[(size_t)Mseq * Dm];           // hidden states
__device__ float g_Ec[Bm * Dm];
__device__ float g_Gc[6 * Bm * Dm];
__device__ float g_Clast[Bm * Dm];
__device__ float g_Hcur[Bm * Dm];
__device__ float g_wt[384];                          // Wtime @ Wg_bot
__device__ float g_bias[384];                        // btime @ Wg_bot + bg
__device__ float g_scanP[Bm * Dm * NC];              // chunk prod(f)
__device__ float g_scanA[Bm * Dm * NC];              // chunk affine term
__device__ float g_scanCin[Bm * Dm * NC];            // chunk entry carry
__device__ unsigned g_WeHi[384 * 64];                // We split: packed bf16x2 (k pairs)
__device__ unsigned g_WeLo[384 * 64];
__device__ unsigned g_WgHi[32 * 384];                // Wg_top split: [kpair][n]
__device__ unsigned g_WgLo[32 * 384];

// ---------------------------------------------------------------------------
// Math helpers
// ---------------------------------------------------------------------------
__device__ __forceinline__ float fast_tanh(float x) {
    float y;
    asm("tanh.approx.f32 %0, %1;" : "=f"(y) : "f"(x));
    return y;
}
__device__ __forceinline__ float fsigmoid(float x) {
    return __fdividef(1.0f, 1.0f + __expf(-x));
}
__device__ __forceinline__ float fsoftplus(float x) {
    return fmaxf(x, 0.0f) + log1pf(__expf(-fabsf(x)));
}
__device__ __forceinline__ float fgelu(float x) {
    return 0.5f * x * (1.0f + erff(x * 0.70710678118654752f));
}
// pack two f32 -> bf16x2 (lo = first element in lower 16 bits)
__device__ __forceinline__ unsigned bfpair(float lo, float hi) {
    unsigned r;
    asm("cvt.rn.bf16x2.f32 %0, %1, %2;" : "=r"(r) : "f"(hi), "f"(lo));
    return r;
}
// split a float2 (consecutive-k pair) into hi/lo bf16x2 regs
__device__ __forceinline__ void split2(float2 e, unsigned& h, unsigned& l) {
    unsigned hp = bfpair(e.x, e.y);
    float h0 = __uint_as_float(hp << 16);
    float h1 = __uint_as_float(hp & 0xFFFF0000u);
    h = hp;
    l = bfpair(e.x - h0, e.y - h1);
}
__device__ __forceinline__ void mma_bf16(float* c, const unsigned* a, unsigned b0, unsigned b1) {
    asm volatile(
        "mma.sync.aligned.m16n8k16.row.col.f32.bf16.bf16.f32 "
        "{%0,%1,%2,%3}, {%4,%5,%6,%7}, {%8,%9}, {%0,%1,%2,%3};"
        : "+f"(c[0]), "+f"(c[1]), "+f"(c[2]), "+f"(c[3])
        : "r"(a[0]), "r"(a[1]), "r"(a[2]), "r"(a[3]), "r"(b0), "r"(b1));
}
__device__ __forceinline__ void cp_async16(void* sdst, const void* gsrc) {
    unsigned sa = (unsigned)__cvta_generic_to_shared(sdst);
    asm volatile("cp.async.cg.shared.global [%0], [%1], 16;" :: "r"(sa), "l"(gsrc) : "memory");
}

// ---------------------------------------------------------------------------
// Merged prologue kernel: one launch does setup + We split + Wg split.
//   items [0,384)            : wt/bias columns
//   items [384, 384+24576)   : We split (t = j*64+n)
//   items [24960, 24960+12288): Wg split (t = j*384+n)
// ---------------------------------------------------------------------------
__global__ __launch_bounds__(256) void prologue_kernel(const float* __restrict__ Wtime,
                                                       const float* __restrict__ btime,
                                                       const float* __restrict__ Wg,
                                                       const float* __restrict__ bg,
                                                       const float* __restrict__ We) {
    int t = blockIdx.x * 256 + threadIdx.x;
    if (t < 384) {
        int c = t;
        float s1 = 0.f, s2 = 0.f;
        #pragma unroll 8
        for (int d = 0; d < 64; d++) {
            float w = Wg[(size_t)(64 + d) * 384 + c];
            s1 += Wtime[d] * w;
            s2 += btime[d] * w;
        }
        g_wt[c] = s1;
        g_bias[c] = s2 + bg[c];
    } else if (t < 384 + 24576) {
        int u = t - 384;
        int j = u >> 6, n = u & 63;
        float2 e = make_float2(We[(size_t)(2 * j) * 64 + n], We[(size_t)(2 * j + 1) * 64 + n]);
        unsigned h, l;
        split2(e, h, l);
        g_WeHi[u] = h;
        g_WeLo[u] = l;
    } else if (t < 384 + 24576 + 12288) {
        int u = t - (384 + 24576);
        int j = u / 384, n = u - j * 384;
        float2 e = make_float2(Wg[(size_t)(2 * j) * 384 + n], Wg[(size_t)(2 * j + 1) * 384 + n]);
        unsigned h, l;
        split2(e, h, l);
        g_WgHi[u] = h;
        g_WgLo[u] = l;
    }
}

// ---------------------------------------------------------------------------
// GEMM1 via bf16-split tensor-core mma + 3-buffer cp.async pipeline
// (prefetch distance 2). Retiled: 8 warps = 8 m-tiles, each warp covers
// 16 rows x 64 cols — every A row split by exactly ONE warp (was 2).
// MERGED: blocks [0,NEVB) = event rows, [NEVB,NEVB+2) = cls rows.
// ---------------------------------------------------------------------------
#define G1_LOAD(s, t) do {                                                        \
    int k0_ = (t) * 16;                                                           \
    {   int m_ = tid >> 2, kv_ = (tid & 3) * 4;                                   \
        cp_async16(&As[s][m_][kv_], A + (r0 + m_) * 768 + k0_ + kv_); }           \
    {   int c_ = tid + 256;                                                       \
        int m_ = c_ >> 2, kv_ = (c_ & 3) * 4;                                     \
        cp_async16(&As[s][m_][kv_], A + (r0 + m_) * 768 + k0_ + kv_); }           \
    if (tid < 128) {                                                              \
        int j_ = tid >> 4, n_ = (tid & 15) * 4;                                   \
        cp_async16(&BsH[s][j_][n_], BHi + (size_t)(t) * 512 + j_ * 64 + n_);      \
    } else {                                                                      \
        int j_ = (tid - 128) >> 4, n_ = ((tid - 128) & 15) * 4;                   \
        cp_async16(&BsL[s][j_][n_], BLo + (size_t)(t) * 512 + j_ * 64 + n_);      \
    }                                                                             \
} while (0)

__global__ __launch_bounds__(256, 3) void gemm1_mma(const float* __restrict__ Aev,
                                                    const float* __restrict__ Acls,
                                                    const unsigned* __restrict__ BHi,
                                                    const unsigned* __restrict__ BLo,
                                                    const float* __restrict__ be,
                                                    float* __restrict__ Cev,
                                                    float* __restrict__ Ccls) {
    __shared__ __align__(16) float As[3][128][20];        // 30.0 KB
    __shared__ __align__(16) unsigned BsH[3][8][64];      // 6.0 KB
    __shared__ __align__(16) unsigned BsL[3][8][64];      // 6.0 KB
    const int tid = threadIdx.x;
    const int wid = tid >> 5, lane = tid & 31;
    const int q = lane & 3, rr = lane >> 2;
    const int rowb = wid * 16 + rr;      // warp = m-tile wid: rows wid*16 .. +15

    const float* A;
    float* C;
    size_t r0;
    if (blockIdx.x < NEVB) {
        A = Aev;  C = Cev;  r0 = (size_t)blockIdx.x * 128;
    } else {
        A = Acls; C = Ccls; r0 = (size_t)(blockIdx.x - NEVB) * 128;
    }

    float acc[8][4];
    #pragma unroll
    for (int nt = 0; nt < 8; nt++)
        #pragma unroll
        for (int i = 0; i < 4; i++) acc[nt][i] = 0.f;

    // prologue: stages 0 and 1 in flight
    G1_LOAD(0, 0);
    asm volatile("cp.async.commit_group;" ::: "memory");
    G1_LOAD(1, 1);
    asm volatile("cp.async.commit_group;" ::: "memory");

    #pragma unroll 3
    for (int t = 0; t < 48; t++) {
        const int cur = t % 3;
        asm volatile("cp.async.wait_group 1;" ::: "memory");   // stage t resident
        __syncthreads();                                        // all warps past stage t-1 reads

        // issue stage t+2 into buffer (t+2)%3 (read finished at iter t-1)
        if (t + 2 < 48) {
            const int nxt = (t + 2) % 3;
            G1_LOAD(nxt, t + 2);
        }
        asm volatile("cp.async.commit_group;" ::: "memory");    // (possibly empty) group

        // A fragments: 4 splits per thread (unique rows per warp)
        unsigned aH[4], aL[4];
        {
            float2 e0 = *reinterpret_cast<const float2*>(&As[cur][rowb][2 * q]);
            float2 e1 = *reinterpret_cast<const float2*>(&As[cur][rowb + 8][2 * q]);
            float2 e2 = *reinterpret_cast<const float2*>(&As[cur][rowb][2 * q + 8]);
            float2 e3 = *reinterpret_cast<const float2*>(&As[cur][rowb + 8][2 * q + 8]);
            split2(e0, aH[0], aL[0]);
            split2(e1, aH[1], aL[1]);
            split2(e2, aH[2], aL[2]);
            split2(e3, aH[3], aL[3]);
        }
        #pragma unroll
        for (int nt = 0; nt < 8; nt++) {
            int c = nt * 8 + rr;
            unsigned bH0 = BsH[cur][q][c], bH1 = BsH[cur][q + 4][c];
            unsigned bL0 = BsL[cur][q][c], bL1 = BsL[cur][q + 4][c];
            mma_bf16(acc[nt], aH, bH0, bH1);
            mma_bf16(acc[nt], aH, bL0, bL1);
            mma_bf16(acc[nt], aL, bH0, bH1);
        }
    }

    // epilogue: + be, direct float2 stores
    #pragma unroll
    for (int nt = 0; nt < 8; nt++) {
        int col = nt * 8 + 2 * q;
        float b0 = be[col], b1 = be[col + 1];
        size_t row = r0 + rowb;
        *reinterpret_cast<float2*>(C + row * 64 + col) =
            make_float2(acc[nt][0] + b0, acc[nt][1] + b1);
        *reinterpret_cast<float2*>(C + (row + 8) * 64 + col) =
            make_float2(acc[nt][2] + b0, acc[nt][3] + b1);
    }
}

// ---------------------------------------------------------------------------
// GEMM2 via bf16-split tensor-core mma (unchanged from R11)
// ---------------------------------------------------------------------------
__global__ __launch_bounds__(256, 2) void gemm2_mma(const float* __restrict__ Eev,
                                                    const float* __restrict__ Ecls,
                                                    const unsigned* __restrict__ WgHi,
                                                    const unsigned* __restrict__ WgLo,
                                                    const float* __restrict__ days_in,
                                                    float* __restrict__ Gev,
                                                    float* __restrict__ Gcls) {
    __shared__ unsigned AsH[128][33], AsL[128][33];
    __shared__ __align__(16) unsigned BsH[8][132], BsL[8][132];
    const int tid = threadIdx.x;
    const int wid = tid >> 5, lane = tid & 31;
    const int warpR = wid >> 1;
    const int warpC = wid & 1;
    const int q = lane & 3, rr = lane >> 2;
    const int n0 = blockIdx.y * 128;

    const float* E;
    const float* days;
    float* gates;
    int M;
    size_t r0;
    if (blockIdx.x < NEVB) {
        E = Eev;  days = days_in; gates = Gev;  M = Mseq;
        r0 = (size_t)blockIdx.x * 128;
    } else {
        E = Ecls; days = nullptr; gates = Gcls; M = Bm;
        r0 = (size_t)(blockIdx.x - NEVB) * 128;
    }

    #pragma unroll
    for (int p = 0; p < 16; p++) {
        int idx = tid + p * 256;
        int m = idx >> 5, j = idx & 31;
        float2 e = *reinterpret_cast<const float2*>(E + (r0 + m) * 64 + 2 * j);
        unsigned h, l;
        split2(e, h, l);
        AsH[m][j] = h;
        AsL[m][j] = l;
    }

    float acc[2][8][4];
    #pragma unroll
    for (int mt = 0; mt < 2; mt++)
        #pragma unroll
        for (int nt = 0; nt < 8; nt++)
            #pragma unroll
            for (int i = 0; i < 4; i++) acc[mt][nt][i] = 0.f;

    #pragma unroll
    for (int c = 0; c < 4; c++) {
        __syncthreads();
        {
            int t4 = tid * 4;
            int jj = t4 >> 7, nn = t4 & 127;
            size_t src = (size_t)(c * 8 + jj) * 384 + n0 + nn;
            *reinterpret_cast<uint4*>(&BsH[jj][nn]) = *reinterpret_cast<const uint4*>(WgHi + src);
            *reinterpret_cast<uint4*>(&BsL[jj][nn]) = *reinterpret_cast<const uint4*>(WgLo + src);
        }
        __syncthreads();

        unsigned aH[2][4], aL[2][4];
        const int jb = c * 8;
        #pragma unroll
        for (int mt = 0; mt < 2; mt++) {
            int row = warpR * 32 + mt * 16 + rr;
            aH[mt][0] = AsH[row][jb + q];         aL[mt][0] = AsL[row][jb + q];
            aH[mt][1] = AsH[row + 8][jb + q];     aL[mt][1] = AsL[row + 8][jb + q];
            aH[mt][2] = AsH[row][jb + q + 4];     aL[mt][2] = AsL[row][jb + q + 4];
            aH[mt][3] = AsH[row + 8][jb + q + 4]; aL[mt][3] = AsL[row + 8][jb + q + 4];
        }
        #pragma unroll
        for (int nt = 0; nt < 8; nt++) {
            int cc = warpC * 64 + nt * 8 + rr;
            unsigned bH0 = BsH[q][cc], bH1 = BsH[q + 4][cc];
            unsigned bL0 = BsL[q][cc], bL1 = BsL[q + 4][cc];
            #pragma unroll
            for (int mt = 0; mt < 2; mt++) {
                mma_bf16(acc[mt][nt], aH[mt], bH0, bH1);
                mma_bf16(acc[mt][nt], aH[mt], bL0, bL1);
                mma_bf16(acc[mt][nt], aL[mt], bH0, bH1);
            }
        }
    }

    const int gate = (n0 + warpC * 64) >> 6;
    float wt16[8][2], bi16[8][2];
    #pragma unroll
    for (int nt = 0; nt < 8; nt++) {
        int col = n0 + warpC * 64 + nt * 8 + 2 * q;
        wt16[nt][0] = g_wt[col];   wt16[nt][1] = g_wt[col + 1];
        bi16[nt][0] = g_bias[col]; bi16[nt][1] = g_bias[col + 1];
    }
    const int d0 = 2 * q;
    #pragma unroll
    for (int mt = 0; mt < 2; mt++) {
        size_t rowb = r0 + warpR * 32 + mt * 16 + rr;
        #pragma unroll
        for (int h = 0; h < 2; h++) {
            size_t rg = rowb + h * 8;
            float dy = days ? days[rg] : 0.f;
            float v[16];
            #pragma unroll
            for (int nt = 0; nt < 8; nt++) {
                v[2 * nt + 0] = acc[mt][nt][2 * h + 0] + bi16[nt][0] + dy * wt16[nt][0];
                v[2 * nt + 1] = acc[mt][nt][2 * h + 1] + bi16[nt][1] + dy * wt16[nt][1];
            }
            if (gate == 2) {
                #pragma unroll
                for (int i = 0; i < 16; i++) v[i] = fast_tanh(v[i]);
            } else if (gate == 4) {
                #pragma unroll
                for (int i = 0; i < 16; i++) v[i] = fsoftplus(v[i]);
            } else if (gate != 5) {
                #pragma unroll
                for (int i = 0; i < 16; i++) v[i] = fsigmoid(v[i]);
            }
            float* dst = gates + ((size_t)gate * M + rg) * 64 + d0;
            #pragma unroll
            for (int nt = 0; nt < 8; nt++)
                *reinterpret_cast<float2*>(dst + nt * 8) = make_float2(v[2 * nt], v[2 * nt + 1]);
        }
    }
}

// ---------------------------------------------------------------------------
// Chunk-parallel CT-LSTM scan (unchanged)
// ---------------------------------------------------------------------------
__global__ __launch_bounds__(256) void scanA_kernel(const float* __restrict__ gates) {
    int t = blockIdx.x * 256 + threadIdx.x;
    int d = t & 63, rest = t >> 6;
    int b = rest & 255, ch = rest >> 8;
    const size_t S = (size_t)Mseq * 64;
    size_t base = ((size_t)(b * Lm + ch * CL)) * 64 + d;
    float c = 0.f, P = 1.f;
    #pragma unroll 5
    for (int l = 0; l < CL; l++) {
        size_t idx = base + (size_t)l * 64;
        float i_ = gates[idx];
        float f_ = gates[S + idx];
        float z_ = gates[2 * S + idx];
        c = f_ * c + i_ * z_;
        P *= f_;
    }
    g_scanA[t] = c;
    g_scanP[t] = P;
}

__global__ __launch_bounds__(256) void scanB_kernel() {
    int t = blockIdx.x * 256 + threadIdx.x;
    float c = 0.f;
    #pragma unroll
    for (int ch = 0; ch < NC; ch++) {
        int q = ch * 16384 + t;
        g_scanCin[q] = c;
        c = g_scanP[q] * c + g_scanA[q];
    }
    g_Clast[t] = c;
}

__global__ __launch_bounds__(256) void scanC_kernel(const float* __restrict__ gates,
                                                    const float* __restrict__ days) {
    int t = blockIdx.x * 256 + threadIdx.x;
    int d = t & 63, rest = t >> 6;
    int b = rest & 255, ch = rest >> 8;
    const size_t S = (size_t)Mseq * 64;
    size_t base = ((size_t)(b * Lm + ch * CL)) * 64 + d;
    const float* dptr = days + b * Lm + ch * CL;
    float c = g_scanCin[t];
    #pragma unroll 5
    for (int l = 0; l < CL; l++) {
        size_t idx = base + (size_t)l * 64;
        float i_ = gates[idx];
        float f_ = gates[S + idx];
        float z_ = gates[2 * S + idx];
        float o_ = gates[3 * S + idx];
        float dl = gates[4 * S + idx];
        float cb = gates[5 * S + idx];
        float dt = fmaxf(dptr[l], 0.f);
        c = f_ * c + i_ * z_;
        float e = __expf(-dl * dt);
        float cd = cb + (c - cb) * e;
        g_Hs[idx] = o_ * fast_tanh(cd);
    }
}

// ---------------------------------------------------------------------------
// Final CT-LSTM step at dt = 0
// ---------------------------------------------------------------------------
__global__ void final_ch_kernel() {
    int b = blockIdx.x, d = threadIdx.x;
    const int S = Bm * 64;
    int idx = b * 64 + d;
    float c = g_Gc[S + idx] * g_Clast[idx] + g_Gc[idx] * g_Gc[2 * S + idx];
    g_Hcur[idx] = g_Gc[3 * S + idx] * fast_tanh(c);
}

// ---------------------------------------------------------------------------
// Intensity MLP (unchanged; Ys aliased into rows buffer)
// ---------------------------------------------------------------------------
__global__ __launch_bounds__(256) void intensity_kernel(const float* __restrict__ src, int M,
                                                        const float* __restrict__ W1,
                                                        const float* __restrict__ b1,
                                                        const float* __restrict__ W2,
                                                        const float* __restrict__ b2,
                                                        float* __restrict__ out) {
    __shared__ __align__(16) float rows[128][68];
    __shared__ __align__(16) float W1s[2048];
    __shared__ float W2s[192], b1s[32], b2s[6];
    float* Ys = &rows[0][0];
    int tid = threadIdx.x;
    size_t r0 = (size_t)blockIdx.x * 128;

    for (int i4 = tid; i4 < 512; i4 += 256)
        *reinterpret_cast<float4*>(&W1s[i4 * 4]) = reinterpret_cast<const float4*>(W1)[i4];
    if (tid < 192) W2s[tid] = W2[tid];
    if (tid < 32) b1s[tid] = b1[tid];
    if (tid < 6) b2s[tid] = b2[tid];
    #pragma unroll
    for (int p = 0; p < 8; p++) {
        int idx = tid + p * 256;
        int m = idx >> 4, dv = (idx & 15) * 4;
        *reinterpret_cast<float4*>(&rows[m][dv]) =
            *reinterpret_cast<const float4*>(src + (r0 + m) * 64 + dv);
    }
    __syncthreads();

    int tr = tid >> 3, tc = tid & 7;
    float acc[4][4];
    #pragma unroll
    for (int i = 0; i < 4; i++)
        #pragma unroll
        for (int j = 0; j < 4; j++) acc[i][j] = b1s[tc * 4 + j];
    #pragma unroll 4
    for (int k = 0; k < 64; k++) {
        float4 w = *reinterpret_cast<const float4*>(&W1s[k * 32 + tc * 4]);
        float a0 = rows[tr * 4 + 0][k];
        float a1 = rows[tr * 4 + 1][k];
        float a2 = rows[tr * 4 + 2][k];
        float a3 = rows[tr * 4 + 3][k];
        acc[0][0] = fmaf(a0, w.x, acc[0][0]); acc[0][1] = fmaf(a0, w.y, acc[0][1]);
        acc[0][2] = fmaf(a0, w.z, acc[0][2]); acc[0][3] = fmaf(a0, w.w, acc[0][3]);
        acc[1][0] = fmaf(a1, w.x, acc[1][0]); acc[1][1] = fmaf(a1, w.y, acc[1][1]);
        acc[1][2] = fmaf(a1, w.z, acc[1][2]); acc[1][3] = fmaf(a1, w.w, acc[1][3]);
        acc[2][0] = fmaf(a2, w.x, acc[2][0]); acc[2][1] = fmaf(a2, w.y, acc[2][1]);
        acc[2][2] = fmaf(a2, w.z, acc[2][2]); acc[2][3] = fmaf(a2, w.w, acc[2][3]);
        acc[3][0] = fmaf(a3, w.x, acc[3][0]); acc[3][1] = fmaf(a3, w.y, acc[3][1]);
        acc[3][2] = fmaf(a3, w.z, acc[3][2]); acc[3][3] = fmaf(a3, w.w, acc[3][3]);
    }
    __syncthreads();
    #pragma unroll
    for (int i = 0; i < 4; i++)
        #pragma unroll
        for (int j = 0; j < 4; j++)
            Ys[(tr * 4 + i) * 33 + tc * 4 + j] = fgelu(acc[i][j]);
    __syncthreads();

    if (tid < 128) {
        int row = tid;
        float o6[6];
        #pragma unroll
        for (int c = 0; c < 6; c++) o6[c] = b2s[c];
        #pragma unroll 4
        for (int k = 0; k < 32; k++) {
            float a = Ys[row * 33 + k];
            #pragma unroll
            for (int c = 0; c < 6; c++) o6[c] = fmaf(a, W2s[k * 6 + c], o6[c]);
        }
        #pragma unroll
        for (int c = 0; c < 6; c++) out[(r0 + row) * 6 + c] = fsoftplus(o6[c]);
    }
}

// ---------------------------------------------------------------------------
// TTE head (unchanged)
// ---------------------------------------------------------------------------
__global__ __launch_bounds__(256) void tte_kernel(const float* __restrict__ W1,
                                                  const float* __restrict__ b1,
                                                  const float* __restrict__ W2,
                                                  const float* __restrict__ b2,
                                                  float* __restrict__ out) {
    __shared__ float W1s[64 * 32];
    __shared__ float W2s[32];
    __shared__ float b1s[32];
    __shared__ float b2s0;
    __shared__ float rows[8][64];
    int tid = threadIdx.x;
    for (int i = tid; i < 2048; i += 256) W1s[i] = W1[i];
    if (tid < 32) { W2s[tid] = W2[tid]; b1s[tid] = b1[tid]; }
    if (tid == 0) b2s0 = b2[0];
    __syncthreads();
    int warp = tid >> 5, lane = tid & 31;
    int b = blockIdx.x * 8 + warp;
    if (b >= Bm) return;
    rows[warp][lane] = g_Hcur[b * 64 + lane];
    rows[warp][lane + 32] = g_Hcur[b * 64 + lane + 32];
    __syncwarp();
    float acc = b1s[lane];
    #pragma unroll
    for (int k = 0; k < 64; k++) acc = fmaf(rows[warp][k], W1s[k * 32 + lane], acc);
    float y = fgelu(acc);
    float p = y * W2s[lane];
    #pragma unroll
    for (int off = 16; off; off >>= 1) p += __shfl_xor_sync(0xffffffffu, p, off);
    if (lane == 0) out[b] = fsoftplus(p + b2s0);
}

// ---------------------------------------------------------------------------
// Direct head + softmax (unchanged)
// ---------------------------------------------------------------------------
__global__ __launch_bounds__(384) void direct_kernel(const float* __restrict__ cls,
                                                     const float* __restrict__ Ws1,
                                                     const float* __restrict__ bs1,
                                                     const float* __restrict__ Ws2,
                                                     const float* __restrict__ bs2,
                                                     const float* __restrict__ ci,
                                                     float* __restrict__ probs) {
    __shared__ float cls_s[4 * 768];
    __shared__ float s1[4][384];
    __shared__ float logit_s[4][6];
    int tid = threadIdx.x;
    int b0 = blockIdx.x * 4;
    for (int idx = tid; idx < 4 * 768; idx += 384)
        cls_s[idx] = cls[(size_t)b0 * 768 + idx];
    __syncthreads();
    float a0 = bs1[tid], a1 = a0, a2 = a0, a3 = a0;
    #pragma unroll 4
    for (int k = 0; k < 768; k++) {
        float w = Ws1[(size_t)k * 384 + tid];
        a0 = fmaf(cls_s[k], w, a0);
        a1 = fmaf(cls_s[768 + k], w, a1);
        a2 = fmaf(cls_s[1536 + k], w, a2);
        a3 = fmaf(cls_s[2304 + k], w, a3);
    }
    s1[0][tid] = fgelu(a0);
    s1[1][tid] = fgelu(a1);
    s1[2][tid] = fgelu(a2);
    s1[3][tid] = fgelu(a3);
    __syncthreads();
    int w = tid >> 5, lane = tid & 31;
    if (w < 6) {
        for (int g = 0; g < 4; g++) {
            float p = 0.f;
            #pragma unroll
            for (int j = lane; j < 384; j += 32) p = fmaf(s1[g][j], Ws2[(size_t)j * 6 + w], p);
            #pragma unroll
            for (int off = 16; off; off >>= 1) p += __shfl_xor_sync(0xffffffffu, p, off);
            if (lane == 0) logit_s[g][w] = p + bs2[w];
        }
    }
    __syncthreads();
    if (tid < 4) {
        int g = tid;
        float x[6], m = -1e30f;
        #pragma unroll
        for (int c = 0; c < 6; c++) {
            x[c] = logit_s[g][c] + logf(ci[(size_t)(b0 + g) * 6 + c]);
            m = fmaxf(m, x[c]);
        }
        float s = 0.f;
        #pragma unroll
        for (int c = 0; c < 6; c++) { x[c] = __expf(x[c] - m); s += x[c]; }
        float inv = __fdividef(1.f, s);
        #pragma unroll
        for (int c = 0; c < 6; c++) probs[(size_t)(b0 + g) * 6 + c] = x[c] * inv;
    }
}

// ---------------------------------------------------------------------------
// Launch
// ---------------------------------------------------------------------------
extern "C" void kernel_launch(void* const* d_in, const int* in_sizes, int n_in,
                              void* d_out, int out_size) {
    const float* cls   = (const float*)d_in[0];
    const float* ev    = (const float*)d_in[1];
    const float* days  = (const float*)d_in[2];
    const float* We    = (const float*)d_in[3];
    const float* be    = (const float*)d_in[4];
    const float* Wtime = (const float*)d_in[5];
    const float* btime = (const float*)d_in[6];
    const float* Wg    = (const float*)d_in[7];
    const float* bg    = (const float*)d_in[8];
    const float* Wi1   = (const float*)d_in[9];
    const float* bi1   = (const float*)d_in[10];
    const float* Wi2   = (const float*)d_in[11];
    const float* bi2   = (const float*)d_in[12];
    const float* Ws1   = (const float*)d_in[13];
    const float* bs1   = (const float*)d_in[14];
    const float* Ws2   = (const float*)d_in[15];
    const float* bs2   = (const float*)d_in[16];
    const float* Wq1   = (const float*)d_in[17];
    const float* bq1   = (const float*)d_in[18];
    const float* Wq2   = (const float*)d_in[19];
    const float* bq2   = (const float*)d_in[20];

    float* out = (float*)d_out;
    float* out_probs = out;
    float* out_tte   = out + 1536;
    float* out_ci    = out + 1536 + 256;
    float* out_hist  = out + 1536 + 256 + 1536;

    float *pE, *pG, *pEc, *pGc, *pHs, *pHcur;
    unsigned *pWeHi, *pWeLo, *pWgHi, *pWgLo;
    cudaGetSymbolAddress((void**)&pE, g_E);
    cudaGetSymbolAddress((void**)&pG, g_G);
    cudaGetSymbolAddress((void**)&pEc, g_Ec);
    cudaGetSymbolAddress((void**)&pGc, g_Gc);
    cudaGetSymbolAddress((void**)&pHs, g_Hs);
    cudaGetSymbolAddress((void**)&pHcur, g_Hcur);
    cudaGetSymbolAddress((void**)&pWeHi, g_WeHi);
    cudaGetSymbolAddress((void**)&pWeLo, g_WeLo);
    cudaGetSymbolAddress((void**)&pWgHi, g_WgHi);
    cudaGetSymbolAddress((void**)&pWgLo, g_WgLo);

    prologue_kernel<<<146, 256>>>(Wtime, btime, Wg, bg, We);

    gemm1_mma<<<NEVB + 2, 256>>>(ev, cls, pWeHi, pWeLo, be, pE, pEc);
    gemm2_mma<<<dim3(NEVB + 2, 3), 256>>>(pE, pEc, pWgHi, pWgLo, days, pG, pGc);

    scanA_kernel<<<(Bm * Dm * NC) / 256, 256>>>(pG);
    scanB_kernel<<<(Bm * Dm) / 256, 256>>>();
    scanC_kernel<<<(Bm * Dm * NC) / 256, 256>>>(pG, days);
    final_ch_kernel<<<Bm, 64>>>();

    intensity_kernel<<<Mseq / 128, 256>>>(pHs, Mseq, Wi1, bi1, Wi2, bi2, out_hist);
    intensity_kernel<<<Bm / 128, 256>>>(pHcur, Bm, Wi1, bi1, Wi2, bi2, out_ci);
    tte_kernel<<<Bm / 8, 256>>>(Wq1, bq1, Wq2, bq2, out_tte);
    direct_kernel<<<Bm / 4, 384>>>(cls, Ws1, bs1, Ws2, bs2, out_ci, out_probs);
}

// round 15
// speedup vs baseline: 1.0868x; 1.0687x over previous
#include <cuda_runtime.h>
#include <cuda_bf16.h>
#include <math.h>
#include <stdint.h>

// ---------------------------------------------------------------------------
// Problem constants
// ---------------------------------------------------------------------------
#define Bm 256
#define Lm 200
#define Hm 768
#define Dm 64
#define NS 6
#define Mseq (Bm * Lm)          // 51200
#define NC 8                    // scan chunks
#define CL 25                   // Lm / NC
#define NEVB (Mseq / 128)       // 400 blocks for the sequence rows

typedef unsigned long long ull;

// ---------------------------------------------------------------------------
// Device scratch (static globals — no allocation allowed)
// ---------------------------------------------------------------------------
__device__ float g_E[(size_t)Mseq * Dm];            // E = ev@We+be
__device__ float g_G[(size_t)6 * Mseq * Dm];        // activated gates (gate, row, d)
__device__ float g_Hs[(size_t)Mseq * Dm];           // hidden states
__device__ float g_Ec[Bm * Dm];
__device__ float g_Gc[6 * Bm * Dm];
__device__ float g_Clast[Bm * Dm];
__device__ float g_Hcur[Bm * Dm];
__device__ float g_wt[384];                          // Wtime @ Wg_bot
__device__ float g_bias[384];                        // btime @ Wg_bot + bg
__device__ float g_scanP[Bm * Dm * NC];              // chunk prod(f)
__device__ float g_scanA[Bm * Dm * NC];              // chunk affine term
__device__ float g_scanCin[Bm * Dm * NC];            // chunk entry carry
__device__ unsigned g_WeHi[384 * 64];                // We split: packed bf16x2 (k pairs)
__device__ unsigned g_WeLo[384 * 64];
__device__ unsigned g_WgHi[32 * 384];                // Wg_top split: [kpair][n]
__device__ unsigned g_WgLo[32 * 384];

// ---------------------------------------------------------------------------
// Math helpers
// ---------------------------------------------------------------------------
__device__ __forceinline__ float fast_tanh(float x) {
    float y;
    asm("tanh.approx.f32 %0, %1;" : "=f"(y) : "f"(x));
    return y;
}
__device__ __forceinline__ float fsigmoid(float x) {
    return __fdividef(1.0f, 1.0f + __expf(-x));
}
__device__ __forceinline__ float fsoftplus(float x) {
    return fmaxf(x, 0.0f) + log1pf(__expf(-fabsf(x)));
}
__device__ __forceinline__ float fgelu(float x) {
    return 0.5f * x * (1.0f + erff(x * 0.70710678118654752f));
}
// pack two f32 -> bf16x2 (lo = first element in lower 16 bits)
__device__ __forceinline__ unsigned bfpair(float lo, float hi) {
    unsigned r;
    asm("cvt.rn.bf16x2.f32 %0, %1, %2;" : "=r"(r) : "f"(hi), "f"(lo));
    return r;
}
// split a float2 (consecutive-k pair) into hi/lo bf16x2 regs
__device__ __forceinline__ void split2(float2 e, unsigned& h, unsigned& l) {
    unsigned hp = bfpair(e.x, e.y);
    float h0 = __uint_as_float(hp << 16);
    float h1 = __uint_as_float(hp & 0xFFFF0000u);
    h = hp;
    l = bfpair(e.x - h0, e.y - h1);
}
__device__ __forceinline__ void mma_bf16(float* c, const unsigned* a, unsigned b0, unsigned b1) {
    asm volatile(
        "mma.sync.aligned.m16n8k16.row.col.f32.bf16.bf16.f32 "
        "{%0,%1,%2,%3}, {%4,%5,%6,%7}, {%8,%9}, {%0,%1,%2,%3};"
        : "+f"(c[0]), "+f"(c[1]), "+f"(c[2]), "+f"(c[3])
        : "r"(a[0]), "r"(a[1]), "r"(a[2]), "r"(a[3]), "r"(b0), "r"(b1));
}
__device__ __forceinline__ void cp_async16(void* sdst, const void* gsrc) {
    unsigned sa = (unsigned)__cvta_generic_to_shared(sdst);
    asm volatile("cp.async.cg.shared.global [%0], [%1], 16;" :: "r"(sa), "l"(gsrc) : "memory");
}

// ---------------------------------------------------------------------------
// Merged prologue kernel: setup + We split + Wg split in one launch.
// ---------------------------------------------------------------------------
__global__ __launch_bounds__(256) void prologue_kernel(const float* __restrict__ Wtime,
                                                       const float* __restrict__ btime,
                                                       const float* __restrict__ Wg,
                                                       const float* __restrict__ bg,
                                                       const float* __restrict__ We) {
    int t = blockIdx.x * 256 + threadIdx.x;
    if (t < 384) {
        int c = t;
        float s1 = 0.f, s2 = 0.f;
        #pragma unroll 8
        for (int d = 0; d < 64; d++) {
            float w = Wg[(size_t)(64 + d) * 384 + c];
            s1 += Wtime[d] * w;
            s2 += btime[d] * w;
        }
        g_wt[c] = s1;
        g_bias[c] = s2 + bg[c];
    } else if (t < 384 + 24576) {
        int u = t - 384;
        int j = u >> 6, n = u & 63;
        float2 e = make_float2(We[(size_t)(2 * j) * 64 + n], We[(size_t)(2 * j + 1) * 64 + n]);
        unsigned h, l;
        split2(e, h, l);
        g_WeHi[u] = h;
        g_WeLo[u] = l;
    } else if (t < 384 + 24576 + 12288) {
        int u = t - (384 + 24576);
        int j = u / 384, n = u - j * 384;
        float2 e = make_float2(Wg[(size_t)(2 * j) * 384 + n], Wg[(size_t)(2 * j + 1) * 384 + n]);
        unsigned h, l;
        split2(e, h, l);
        g_WgHi[u] = h;
        g_WgLo[u] = l;
    }
}

// ---------------------------------------------------------------------------
// GEMM1: R11 tiling (8 warps in 4x2 grid, warp = 32 rows x 32 cols) +
// 3-buffer cp.async pipeline + XOR-swizzled B panels (conflict-free reads):
//   B row j stored with columns rotated by j*8:  pos = (n + j*8) & 63.
//   Read bank = (c + q*8) & 31 -> q*8+rr enumerates all 32 banks.
// MERGED: blocks [0,NEVB) = event rows, [NEVB,NEVB+2) = cls rows.
// ---------------------------------------------------------------------------
#define G1_LOAD(s, t) do {                                                        \
    int k0_ = (t) * 16;                                                           \
    {   int m_ = tid >> 2, kv_ = (tid & 3) * 4;                                   \
        cp_async16(&As[s][m_][kv_], A + (r0 + m_) * 768 + k0_ + kv_); }           \
    {   int c_ = tid + 256;                                                       \
        int m_ = c_ >> 2, kv_ = (c_ & 3) * 4;                                     \
        cp_async16(&As[s][m_][kv_], A + (r0 + m_) * 768 + k0_ + kv_); }           \
    if (tid < 128) {                                                              \
        int j_ = tid >> 4, n_ = (tid & 15) * 4;                                   \
        int sw_ = (n_ + j_ * 8) & 63;                                             \
        cp_async16(&BsH[s][j_][sw_], BHi + (size_t)(t) * 512 + j_ * 64 + n_);     \
    } else {                                                                      \
        int j_ = (tid - 128) >> 4, n_ = ((tid - 128) & 15) * 4;                   \
        int sw_ = (n_ + j_ * 8) & 63;                                             \
        cp_async16(&BsL[s][j_][sw_], BLo + (size_t)(t) * 512 + j_ * 64 + n_);     \
    }                                                                             \
} while (0)

__global__ __launch_bounds__(256, 3) void gemm1_mma(const float* __restrict__ Aev,
                                                    const float* __restrict__ Acls,
                                                    const unsigned* __restrict__ BHi,
                                                    const unsigned* __restrict__ BLo,
                                                    const float* __restrict__ be,
                                                    float* __restrict__ Cev,
                                                    float* __restrict__ Ccls) {
    __shared__ __align__(16) float As[3][128][20];        // 30.0 KB
    __shared__ __align__(16) unsigned BsH[3][8][64];      // 6.0 KB (swizzled cols)
    __shared__ __align__(16) unsigned BsL[3][8][64];      // 6.0 KB (swizzled cols)
    const int tid = threadIdx.x;
    const int wid = tid >> 5, lane = tid & 31;
    const int warpR = wid >> 1;          // 0..3 : rows warpR*32
    const int warpC = wid & 1;           // 0..1 : cols warpC*32
    const int q = lane & 3, rr = lane >> 2;

    const float* A;
    float* C;
    size_t r0;
    if (blockIdx.x < NEVB) {
        A = Aev;  C = Cev;  r0 = (size_t)blockIdx.x * 128;
    } else {
        A = Acls; C = Ccls; r0 = (size_t)(blockIdx.x - NEVB) * 128;
    }

    float acc[2][4][4];
    #pragma unroll
    for (int mt = 0; mt < 2; mt++)
        #pragma unroll
        for (int nt = 0; nt < 4; nt++)
            #pragma unroll
            for (int i = 0; i < 4; i++) acc[mt][nt][i] = 0.f;

    // prologue: stages 0 and 1 in flight
    G1_LOAD(0, 0);
    asm volatile("cp.async.commit_group;" ::: "memory");
    G1_LOAD(1, 1);
    asm volatile("cp.async.commit_group;" ::: "memory");

    // swizzled read columns for this thread (rows q and q+4)
    const int swA = q * 8;          // shift for row q
    const int swB = (q + 4) * 8;    // shift for row q+4

    #pragma unroll 3
    for (int t = 0; t < 48; t++) {
        const int cur = t % 3;
        asm volatile("cp.async.wait_group 1;" ::: "memory");   // stage t resident
        __syncthreads();                                        // all warps past stage t-1 reads

        if (t + 2 < 48) {
            const int nxt = (t + 2) % 3;
            G1_LOAD(nxt, t + 2);
        }
        asm volatile("cp.async.commit_group;" ::: "memory");

        // A fragments (hi/lo) for 2 m-tiles
        unsigned aH[2][4], aL[2][4];
        #pragma unroll
        for (int mt = 0; mt < 2; mt++) {
            int row = warpR * 32 + mt * 16 + rr;
            #pragma unroll
            for (int kk = 0; kk < 2; kk++) {
                float2 e0 = *reinterpret_cast<const float2*>(&As[cur][row][2 * q + 8 * kk]);
                float2 e1 = *reinterpret_cast<const float2*>(&As[cur][row + 8][2 * q + 8 * kk]);
                split2(e0, aH[mt][2 * kk + 0], aL[mt][2 * kk + 0]);
                split2(e1, aH[mt][2 * kk + 1], aL[mt][2 * kk + 1]);
            }
        }
        #pragma unroll
        for (int nt = 0; nt < 4; nt++) {
            int c = warpC * 32 + nt * 8 + rr;
            unsigned bH0 = BsH[cur][q][(c + swA) & 63];
            unsigned bH1 = BsH[cur][q + 4][(c + swB) & 63];
            unsigned bL0 = BsL[cur][q][(c + swA) & 63];
            unsigned bL1 = BsL[cur][q + 4][(c + swB) & 63];
            #pragma unroll
            for (int mt = 0; mt < 2; mt++) {
                mma_bf16(acc[mt][nt], aH[mt], bH0, bH1);
                mma_bf16(acc[mt][nt], aH[mt], bL0, bL1);
                mma_bf16(acc[mt][nt], aL[mt], bH0, bH1);
            }
        }
    }

    // epilogue: + be, direct float2 stores
    #pragma unroll
    for (int nt = 0; nt < 4; nt++) {
        int col = warpC * 32 + nt * 8 + 2 * q;
        float b0 = be[col], b1 = be[col + 1];
        #pragma unroll
        for (int mt = 0; mt < 2; mt++) {
            size_t row = r0 + warpR * 32 + mt * 16 + rr;
            *reinterpret_cast<float2*>(C + row * 64 + col) =
                make_float2(acc[mt][nt][0] + b0, acc[mt][nt][1] + b1);
            *reinterpret_cast<float2*>(C + (row + 8) * 64 + col) =
                make_float2(acc[mt][nt][2] + b0, acc[mt][nt][3] + b1);
        }
    }
}

// ---------------------------------------------------------------------------
// GEMM2 via bf16-split tensor-core mma (unchanged from R11)
// ---------------------------------------------------------------------------
__global__ __launch_bounds__(256, 2) void gemm2_mma(const float* __restrict__ Eev,
                                                    const float* __restrict__ Ecls,
                                                    const unsigned* __restrict__ WgHi,
                                                    const unsigned* __restrict__ WgLo,
                                                    const float* __restrict__ days_in,
                                                    float* __restrict__ Gev,
                                                    float* __restrict__ Gcls) {
    __shared__ unsigned AsH[128][33], AsL[128][33];
    __shared__ __align__(16) unsigned BsH[8][132], BsL[8][132];
    const int tid = threadIdx.x;
    const int wid = tid >> 5, lane = tid & 31;
    const int warpR = wid >> 1;
    const int warpC = wid & 1;
    const int q = lane & 3, rr = lane >> 2;
    const int n0 = blockIdx.y * 128;

    const float* E;
    const float* days;
    float* gates;
    int M;
    size_t r0;
    if (blockIdx.x < NEVB) {
        E = Eev;  days = days_in; gates = Gev;  M = Mseq;
        r0 = (size_t)blockIdx.x * 128;
    } else {
        E = Ecls; days = nullptr; gates = Gcls; M = Bm;
        r0 = (size_t)(blockIdx.x - NEVB) * 128;
    }

    #pragma unroll
    for (int p = 0; p < 16; p++) {
        int idx = tid + p * 256;
        int m = idx >> 5, j = idx & 31;
        float2 e = *reinterpret_cast<const float2*>(E + (r0 + m) * 64 + 2 * j);
        unsigned h, l;
        split2(e, h, l);
        AsH[m][j] = h;
        AsL[m][j] = l;
    }

    float acc[2][8][4];
    #pragma unroll
    for (int mt = 0; mt < 2; mt++)
        #pragma unroll
        for (int nt = 0; nt < 8; nt++)
            #pragma unroll
            for (int i = 0; i < 4; i++) acc[mt][nt][i] = 0.f;

    #pragma unroll
    for (int c = 0; c < 4; c++) {
        __syncthreads();
        {
            int t4 = tid * 4;
            int jj = t4 >> 7, nn = t4 & 127;
            size_t src = (size_t)(c * 8 + jj) * 384 + n0 + nn;
            *reinterpret_cast<uint4*>(&BsH[jj][nn]) = *reinterpret_cast<const uint4*>(WgHi + src);
            *reinterpret_cast<uint4*>(&BsL[jj][nn]) = *reinterpret_cast<const uint4*>(WgLo + src);
        }
        __syncthreads();

        unsigned aH[2][4], aL[2][4];
        const int jb = c * 8;
        #pragma unroll
        for (int mt = 0; mt < 2; mt++) {
            int row = warpR * 32 + mt * 16 + rr;
            aH[mt][0] = AsH[row][jb + q];         aL[mt][0] = AsL[row][jb + q];
            aH[mt][1] = AsH[row + 8][jb + q];     aL[mt][1] = AsL[row + 8][jb + q];
            aH[mt][2] = AsH[row][jb + q + 4];     aL[mt][2] = AsL[row][jb + q + 4];
            aH[mt][3] = AsH[row + 8][jb + q + 4]; aL[mt][3] = AsL[row + 8][jb + q + 4];
        }
        #pragma unroll
        for (int nt = 0; nt < 8; nt++) {
            int cc = warpC * 64 + nt * 8 + rr;
            unsigned bH0 = BsH[q][cc], bH1 = BsH[q + 4][cc];
            unsigned bL0 = BsL[q][cc], bL1 = BsL[q + 4][cc];
            #pragma unroll
            for (int mt = 0; mt < 2; mt++) {
                mma_bf16(acc[mt][nt], aH[mt], bH0, bH1);
                mma_bf16(acc[mt][nt], aH[mt], bL0, bL1);
                mma_bf16(acc[mt][nt], aL[mt], bH0, bH1);
            }
        }
    }

    const int gate = (n0 + warpC * 64) >> 6;
    float wt16[8][2], bi16[8][2];
    #pragma unroll
    for (int nt = 0; nt < 8; nt++) {
        int col = n0 + warpC * 64 + nt * 8 + 2 * q;
        wt16[nt][0] = g_wt[col];   wt16[nt][1] = g_wt[col + 1];
        bi16[nt][0] = g_bias[col]; bi16[nt][1] = g_bias[col + 1];
    }
    const int d0 = 2 * q;
    #pragma unroll
    for (int mt = 0; mt < 2; mt++) {
        size_t rowb = r0 + warpR * 32 + mt * 16 + rr;
        #pragma unroll
        for (int h = 0; h < 2; h++) {
            size_t rg = rowb + h * 8;
            float dy = days ? days[rg] : 0.f;
            float v[16];
            #pragma unroll
            for (int nt = 0; nt < 8; nt++) {
                v[2 * nt + 0] = acc[mt][nt][2 * h + 0] + bi16[nt][0] + dy * wt16[nt][0];
                v[2 * nt + 1] = acc[mt][nt][2 * h + 1] + bi16[nt][1] + dy * wt16[nt][1];
            }
            if (gate == 2) {
                #pragma unroll
                for (int i = 0; i < 16; i++) v[i] = fast_tanh(v[i]);
            } else if (gate == 4) {
                #pragma unroll
                for (int i = 0; i < 16; i++) v[i] = fsoftplus(v[i]);
            } else if (gate != 5) {
                #pragma unroll
                for (int i = 0; i < 16; i++) v[i] = fsigmoid(v[i]);
            }
            float* dst = gates + ((size_t)gate * M + rg) * 64 + d0;
            #pragma unroll
            for (int nt = 0; nt < 8; nt++)
                *reinterpret_cast<float2*>(dst + nt * 8) = make_float2(v[2 * nt], v[2 * nt + 1]);
        }
    }
}

// ---------------------------------------------------------------------------
// Chunk-parallel CT-LSTM scan (unchanged)
// ---------------------------------------------------------------------------
__global__ __launch_bounds__(256) void scanA_kernel(const float* __restrict__ gates) {
    int t = blockIdx.x * 256 + threadIdx.x;
    int d = t & 63, rest = t >> 6;
    int b = rest & 255, ch = rest >> 8;
    const size_t S = (size_t)Mseq * 64;
    size_t base = ((size_t)(b * Lm + ch * CL)) * 64 + d;
    float c = 0.f, P = 1.f;
    #pragma unroll 5
    for (int l = 0; l < CL; l++) {
        size_t idx = base + (size_t)l * 64;
        float i_ = gates[idx];
        float f_ = gates[S + idx];
        float z_ = gates[2 * S + idx];
        c = f_ * c + i_ * z_;
        P *= f_;
    }
    g_scanA[t] = c;
    g_scanP[t] = P;
}

__global__ __launch_bounds__(256) void scanB_kernel() {
    int t = blockIdx.x * 256 + threadIdx.x;
    float c = 0.f;
    #pragma unroll
    for (int ch = 0; ch < NC; ch++) {
        int q = ch * 16384 + t;
        g_scanCin[q] = c;
        c = g_scanP[q] * c + g_scanA[q];
    }
    g_Clast[t] = c;
}

__global__ __launch_bounds__(256) void scanC_kernel(const float* __restrict__ gates,
                                                    const float* __restrict__ days) {
    int t = blockIdx.x * 256 + threadIdx.x;
    int d = t & 63, rest = t >> 6;
    int b = rest & 255, ch = rest >> 8;
    const size_t S = (size_t)Mseq * 64;
    size_t base = ((size_t)(b * Lm + ch * CL)) * 64 + d;
    const float* dptr = days + b * Lm + ch * CL;
    float c = g_scanCin[t];
    #pragma unroll 5
    for (int l = 0; l < CL; l++) {
        size_t idx = base + (size_t)l * 64;
        float i_ = gates[idx];
        float f_ = gates[S + idx];
        float z_ = gates[2 * S + idx];
        float o_ = gates[3 * S + idx];
        float dl = gates[4 * S + idx];
        float cb = gates[5 * S + idx];
        float dt = fmaxf(dptr[l], 0.f);
        c = f_ * c + i_ * z_;
        float e = __expf(-dl * dt);
        float cd = cb + (c - cb) * e;
        g_Hs[idx] = o_ * fast_tanh(cd);
    }
}

// ---------------------------------------------------------------------------
// Final CT-LSTM step at dt = 0
// ---------------------------------------------------------------------------
__global__ void final_ch_kernel() {
    int b = blockIdx.x, d = threadIdx.x;
    const int S = Bm * 64;
    int idx = b * 64 + d;
    float c = g_Gc[S + idx] * g_Clast[idx] + g_Gc[idx] * g_Gc[2 * S + idx];
    g_Hcur[idx] = g_Gc[3 * S + idx] * fast_tanh(c);
}

// ---------------------------------------------------------------------------
// Intensity MLP (unchanged; Ys aliased into rows buffer)
// ---------------------------------------------------------------------------
__global__ __launch_bounds__(256) void intensity_kernel(const float* __restrict__ src, int M,
                                                        const float* __restrict__ W1,
                                                        const float* __restrict__ b1,
                                                        const float* __restrict__ W2,
                                                        const float* __restrict__ b2,
                                                        float* __restrict__ out) {
    __shared__ __align__(16) float rows[128][68];
    __shared__ __align__(16) float W1s[2048];
    __shared__ float W2s[192], b1s[32], b2s[6];
    float* Ys = &rows[0][0];
    int tid = threadIdx.x;
    size_t r0 = (size_t)blockIdx.x * 128;

    for (int i4 = tid; i4 < 512; i4 += 256)
        *reinterpret_cast<float4*>(&W1s[i4 * 4]) = reinterpret_cast<const float4*>(W1)[i4];
    if (tid < 192) W2s[tid] = W2[tid];
    if (tid < 32) b1s[tid] = b1[tid];
    if (tid < 6) b2s[tid] = b2[tid];
    #pragma unroll
    for (int p = 0; p < 8; p++) {
        int idx = tid + p * 256;
        int m = idx >> 4, dv = (idx & 15) * 4;
        *reinterpret_cast<float4*>(&rows[m][dv]) =
            *reinterpret_cast<const float4*>(src + (r0 + m) * 64 + dv);
    }
    __syncthreads();

    int tr = tid >> 3, tc = tid & 7;
    float acc[4][4];
    #pragma unroll
    for (int i = 0; i < 4; i++)
        #pragma unroll
        for (int j = 0; j < 4; j++) acc[i][j] = b1s[tc * 4 + j];
    #pragma unroll 4
    for (int k = 0; k < 64; k++) {
        float4 w = *reinterpret_cast<const float4*>(&W1s[k * 32 + tc * 4]);
        float a0 = rows[tr * 4 + 0][k];
        float a1 = rows[tr * 4 + 1][k];
        float a2 = rows[tr * 4 + 2][k];
        float a3 = rows[tr * 4 + 3][k];
        acc[0][0] = fmaf(a0, w.x, acc[0][0]); acc[0][1] = fmaf(a0, w.y, acc[0][1]);
        acc[0][2] = fmaf(a0, w.z, acc[0][2]); acc[0][3] = fmaf(a0, w.w, acc[0][3]);
        acc[1][0] = fmaf(a1, w.x, acc[1][0]); acc[1][1] = fmaf(a1, w.y, acc[1][1]);
        acc[1][2] = fmaf(a1, w.z, acc[1][2]); acc[1][3] = fmaf(a1, w.w, acc[1][3]);
        acc[2][0] = fmaf(a2, w.x, acc[2][0]); acc[2][1] = fmaf(a2, w.y, acc[2][1]);
        acc[2][2] = fmaf(a2, w.z, acc[2][2]); acc[2][3] = fmaf(a2, w.w, acc[2][3]);
        acc[3][0] = fmaf(a3, w.x, acc[3][0]); acc[3][1] = fmaf(a3, w.y, acc[3][1]);
        acc[3][2] = fmaf(a3, w.z, acc[3][2]); acc[3][3] = fmaf(a3, w.w, acc[3][3]);
    }
    __syncthreads();
    #pragma unroll
    for (int i = 0; i < 4; i++)
        #pragma unroll
        for (int j = 0; j < 4; j++)
            Ys[(tr * 4 + i) * 33 + tc * 4 + j] = fgelu(acc[i][j]);
    __syncthreads();

    if (tid < 128) {
        int row = tid;
        float o6[6];
        #pragma unroll
        for (int c = 0; c < 6; c++) o6[c] = b2s[c];
        #pragma unroll 4
        for (int k = 0; k < 32; k++) {
            float a = Ys[row * 33 + k];
            #pragma unroll
            for (int c = 0; c < 6; c++) o6[c] = fmaf(a, W2s[k * 6 + c], o6[c]);
        }
        #pragma unroll
        for (int c = 0; c < 6; c++) out[(r0 + row) * 6 + c] = fsoftplus(o6[c]);
    }
}

// ---------------------------------------------------------------------------
// TTE head (unchanged)
// ---------------------------------------------------------------------------
__global__ __launch_bounds__(256) void tte_kernel(const float* __restrict__ W1,
                                                  const float* __restrict__ b1,
                                                  const float* __restrict__ W2,
                                                  const float* __restrict__ b2,
                                                  float* __restrict__ out) {
    __shared__ float W1s[64 * 32];
    __shared__ float W2s[32];
    __shared__ float b1s[32];
    __shared__ float b2s0;
    __shared__ float rows[8][64];
    int tid = threadIdx.x;
    for (int i = tid; i < 2048; i += 256) W1s[i] = W1[i];
    if (tid < 32) { W2s[tid] = W2[tid]; b1s[tid] = b1[tid]; }
    if (tid == 0) b2s0 = b2[0];
    __syncthreads();
    int warp = tid >> 5, lane = tid & 31;
    int b = blockIdx.x * 8 + warp;
    if (b >= Bm) return;
    rows[warp][lane] = g_Hcur[b * 64 + lane];
    rows[warp][lane + 32] = g_Hcur[b * 64 + lane + 32];
    __syncwarp();
    float acc = b1s[lane];
    #pragma unroll
    for (int k = 0; k < 64; k++) acc = fmaf(rows[warp][k], W1s[k * 32 + lane], acc);
    float y = fgelu(acc);
    float p = y * W2s[lane];
    #pragma unroll
    for (int off = 16; off; off >>= 1) p += __shfl_xor_sync(0xffffffffu, p, off);
    if (lane == 0) out[b] = fsoftplus(p + b2s0);
}

// ---------------------------------------------------------------------------
// Direct head + softmax (unchanged)
// ---------------------------------------------------------------------------
__global__ __launch_bounds__(384) void direct_kernel(const float* __restrict__ cls,
                                                     const float* __restrict__ Ws1,
                                                     const float* __restrict__ bs1,
                                                     const float* __restrict__ Ws2,
                                                     const float* __restrict__ bs2,
                                                     const float* __restrict__ ci,
                                                     float* __restrict__ probs) {
    __shared__ float cls_s[4 * 768];
    __shared__ float s1[4][384];
    __shared__ float logit_s[4][6];
    int tid = threadIdx.x;
    int b0 = blockIdx.x * 4;
    for (int idx = tid; idx < 4 * 768; idx += 384)
        cls_s[idx] = cls[(size_t)b0 * 768 + idx];
    __syncthreads();
    float a0 = bs1[tid], a1 = a0, a2 = a0, a3 = a0;
    #pragma unroll 4
    for (int k = 0; k < 768; k++) {
        float w = Ws1[(size_t)k * 384 + tid];
        a0 = fmaf(cls_s[k], w, a0);
        a1 = fmaf(cls_s[768 + k], w, a1);
        a2 = fmaf(cls_s[1536 + k], w, a2);
        a3 = fmaf(cls_s[2304 + k], w, a3);
    }
    s1[0][tid] = fgelu(a0);
    s1[1][tid] = fgelu(a1);
    s1[2][tid] = fgelu(a2);
    s1[3][tid] = fgelu(a3);
    __syncthreads();
    int w = tid >> 5, lane = tid & 31;
    if (w < 6) {
        for (int g = 0; g < 4; g++) {
            float p = 0.f;
            #pragma unroll
            for (int j = lane; j < 384; j += 32) p = fmaf(s1[g][j], Ws2[(size_t)j * 6 + w], p);
            #pragma unroll
            for (int off = 16; off; off >>= 1) p += __shfl_xor_sync(0xffffffffu, p, off);
            if (lane == 0) logit_s[g][w] = p + bs2[w];
        }
    }
    __syncthreads();
    if (tid < 4) {
        int g = tid;
        float x[6], m = -1e30f;
        #pragma unroll
        for (int c = 0; c < 6; c++) {
            x[c] = logit_s[g][c] + logf(ci[(size_t)(b0 + g) * 6 + c]);
            m = fmaxf(m, x[c]);
        }
        float s = 0.f;
        #pragma unroll
        for (int c = 0; c < 6; c++) { x[c] = __expf(x[c] - m); s += x[c]; }
        float inv = __fdividef(1.f, s);
        #pragma unroll
        for (int c = 0; c < 6; c++) probs[(size_t)(b0 + g) * 6 + c] = x[c] * inv;
    }
}

// ---------------------------------------------------------------------------
// Launch
// ---------------------------------------------------------------------------
extern "C" void kernel_launch(void* const* d_in, const int* in_sizes, int n_in,
                              void* d_out, int out_size) {
    const float* cls   = (const float*)d_in[0];
    const float* ev    = (const float*)d_in[1];
    const float* days  = (const float*)d_in[2];
    const float* We    = (const float*)d_in[3];
    const float* be    = (const float*)d_in[4];
    const float* Wtime = (const float*)d_in[5];
    const float* btime = (const float*)d_in[6];
    const float* Wg    = (const float*)d_in[7];
    const float* bg    = (const float*)d_in[8];
    const float* Wi1   = (const float*)d_in[9];
    const float* bi1   = (const float*)d_in[10];
    const float* Wi2   = (const float*)d_in[11];
    const float* bi2   = (const float*)d_in[12];
    const float* Ws1   = (const float*)d_in[13];
    const float* bs1   = (const float*)d_in[14];
    const float* Ws2   = (const float*)d_in[15];
    const float* bs2   = (const float*)d_in[16];
    const float* Wq1   = (const float*)d_in[17];
    const float* bq1   = (const float*)d_in[18];
    const float* Wq2   = (const float*)d_in[19];
    const float* bq2   = (const float*)d_in[20];

    float* out = (float*)d_out;
    float* out_probs = out;
    float* out_tte   = out + 1536;
    float* out_ci    = out + 1536 + 256;
    float* out_hist  = out + 1536 + 256 + 1536;

    float *pE, *pG, *pEc, *pGc, *pHs, *pHcur;
    unsigned *pWeHi, *pWeLo, *pWgHi, *pWgLo;
    cudaGetSymbolAddress((void**)&pE, g_E);
    cudaGetSymbolAddress((void**)&pG, g_G);
    cudaGetSymbolAddress((void**)&pEc, g_Ec);
    cudaGetSymbolAddress((void**)&pGc, g_Gc);
    cudaGetSymbolAddress((void**)&pHs, g_Hs);
    cudaGetSymbolAddress((void**)&pHcur, g_Hcur);
    cudaGetSymbolAddress((void**)&pWeHi, g_WeHi);
    cudaGetSymbolAddress((void**)&pWeLo, g_WeLo);
    cudaGetSymbolAddress((void**)&pWgHi, g_WgHi);
    cudaGetSymbolAddress((void**)&pWgLo, g_WgLo);

    prologue_kernel<<<146, 256>>>(Wtime, btime, Wg, bg, We);

    gemm1_mma<<<NEVB + 2, 256>>>(ev, cls, pWeHi, pWeLo, be, pE, pEc);
    gemm2_mma<<<dim3(NEVB + 2, 3), 256>>>(pE, pEc, pWgHi, pWgLo, days, pG, pGc);

    scanA_kernel<<<(Bm * Dm * NC) / 256, 256>>>(pG);
    scanB_kernel<<<(Bm * Dm) / 256, 256>>>();
    scanC_kernel<<<(Bm * Dm * NC) / 256, 256>>>(pG, days);
    final_ch_kernel<<<Bm, 64>>>();

    intensity_kernel<<<Mseq / 128, 256>>>(pHs, Mseq, Wi1, bi1, Wi2, bi2, out_hist);
    intensity_kernel<<<Bm / 128, 256>>>(pHcur, Bm, Wi1, bi1, Wi2, bi2, out_ci);
    tte_kernel<<<Bm / 8, 256>>>(Wq1, bq1, Wq2, bq2, out_tte);
    direct_kernel<<<Bm / 4, 384>>>(cls, Ws1, bs1, Ws2, bs2, out_ci, out_probs);
}